// round 10
// baseline (speedup 1.0000x reference)
#include <cuda_runtime.h>
#include <cstddef>
#include <cstdint>

// ---------------------------------------------------------------------------
// Problem constants: B=4, S=8192, D=512, H=8, HD=64, W=128.
// MT = 32768 tokens, 256 windows of 128.
// ---------------------------------------------------------------------------
#define MT 32768
#define DD 512
#define D3 1536
#define DF 2048

// ---------------------------------------------------------------------------
// Scratch (device globals — allocation-free per harness rules)
// ---------------------------------------------------------------------------
__device__ float g_qkv [(size_t)MT * D3];     // f32 qkv for attention
__device__ float g_attn[(size_t)MT * DD];     // f32 attention output
__device__ float g_x1  [(size_t)MT * DD];     // f32 ln1 output (FFN residual)
__device__ float g_resb[(size_t)MT * DD];     // f32 pre-LN buffer
__device__ float g_ff  [(size_t)MT * DF];     // f32 ffn mid (post-ReLU)

// int8 2-plane quant: x ~= s_row * (p0 + p1/254)
__device__ int8_t g_sa0[(size_t)MT * DD], g_sa1[(size_t)MT * DD];   // src
__device__ int8_t g_at0[(size_t)MT * DD], g_at1[(size_t)MT * DD];   // attn out
__device__ int8_t g_xq0[(size_t)MT * DD], g_xq1[(size_t)MT * DD];   // ln1 out
__device__ int8_t g_fq0[(size_t)MT * DF], g_fq1[(size_t)MT * DF];   // ffn mid
__device__ int8_t g_q0 [D3 * DD], g_q1 [D3 * DD];                   // wqkv
__device__ int8_t g_o0 [DD * DD], g_o1 [DD * DD];                   // wout
__device__ int8_t g_u0 [DF * DD], g_u1 [DF * DD];                   // w1
__device__ int8_t g_d0 [DD * DF], g_d1 [DD * DF];                   // w2
// per-row scales
__device__ float g_ssrc[MT], g_sattn[MT], g_sx[MT], g_sff[MT];
__device__ float g_swq[D3], g_swo[DD], g_sw1[DF], g_sw2[DD];

// ---------------------------------------------------------------------------
// PTX helpers (plain-compute_103 features: cp.async / ldmatrix / mma.sync)
// ---------------------------------------------------------------------------
__device__ __forceinline__ uint32_t cvta_s(const void* p) {
    uint32_t a;
    asm("{ .reg .u64 t; cvta.to.shared.u64 t, %1; cvt.u32.u64 %0, t; }"
        : "=r"(a) : "l"(p));
    return a;
}
__device__ __forceinline__ void cp16(uint32_t dst, const void* src) {
    asm volatile("cp.async.cg.shared.global [%0], [%1], 16;"
                 :: "r"(dst), "l"(src));
}
__device__ __forceinline__ void ldsm_x4(uint32_t* r, uint32_t addr) {
    asm volatile("ldmatrix.sync.aligned.m8n8.x4.shared.b16 {%0,%1,%2,%3}, [%4];"
                 : "=r"(r[0]), "=r"(r[1]), "=r"(r[2]), "=r"(r[3]) : "r"(addr));
}
// s8 MMA, s32 accumulate: D[16,8] += A[16,32] * B[32,8]
__device__ __forceinline__ void mma_s8(int* d, const uint32_t* a,
                                       const uint32_t* b) {
    asm volatile(
        "mma.sync.aligned.m16n8k32.row.col.s32.s8.s8.s32 "
        "{%0,%1,%2,%3}, {%4,%5,%6,%7}, {%8,%9}, {%0,%1,%2,%3};"
        : "+r"(d[0]), "+r"(d[1]), "+r"(d[2]), "+r"(d[3])
        : "r"(a[0]), "r"(a[1]), "r"(a[2]), "r"(a[3]), "r"(b[0]), "r"(b[1]));
}

__device__ __forceinline__ int8_t q_clamp(int v) {
    return (int8_t)max(-127, min(127, v));
}

// ---------------------------------------------------------------------------
// IMMA int8x3 GEMM: C[m,n] = sum_k A[m,k]*B[n,k] + bias[n] (+ epilogue)
//   A,B as 2-plane int8 (p0 + p1/254, scale per row), K-major. Fragment
//   byte-mapping of m16n8k32.s8 == bf16 k16 case (4 bytes/lane-reg), so the
//   PROVEN ldmatrix addressing carries over unchanged; K-chunk is now 128
//   bytes.  CTA tile 128x128, 2-stage cp.async, 8 warps (2M x 4N), warp tile
//   64x32, 3 products: P00 -> accm; P01+P10 -> accc (shared /254 scale).
//   EPI 0: bias -> f32     EPI 1: bias + ReLU -> f32     EPI 2: bias + res -> f32
// ---------------------------------------------------------------------------
static constexpr int STAGE = 65536;   // A0 16K | A1 16K | B0 16K | B1 16K

__device__ __forceinline__ void load_chunk(
    const int8_t* __restrict__ A0, const int8_t* __restrict__ A1,
    const int8_t* __restrict__ B0, const int8_t* __restrict__ B1,
    int m0, int n0, int K, int k0, int tid, uint32_t sb)
{
#pragma unroll
    for (int j = 0; j < 4; j++) {
        int id  = tid + 256 * j;          // 0..1023
        int row = id >> 3;                // 0..127
        int c   = id & 7;                 // 16B chunk within 128B row
        uint32_t soff = (uint32_t)(row * 128 + ((c ^ (row & 7)) << 4));
        size_t ga = (size_t)(m0 + row) * K + k0 + c * 16;
        size_t gb = (size_t)(n0 + row) * K + k0 + c * 16;
        cp16(sb + soff,          A0 + ga);
        cp16(sb + 16384 + soff,  A1 + ga);
        cp16(sb + 32768 + soff,  B0 + gb);
        cp16(sb + 49152 + soff,  B1 + gb);
    }
    asm volatile("cp.async.commit_group;" ::: "memory");
}

template <int EPI>
__global__ void __launch_bounds__(256)
tc_gemm(const int8_t* __restrict__ A0, const int8_t* __restrict__ A1,
        const float* __restrict__ sa,
        const int8_t* __restrict__ B0, const int8_t* __restrict__ B1,
        const float* __restrict__ sb_,
        const float* __restrict__ bias, const float* __restrict__ res,
        float* __restrict__ Cf, int N, int K)
{
    extern __shared__ __align__(1024) char dyn_smem[];
    uint32_t sbase = (cvta_s(dyn_smem) + 1023u) & ~1023u;

    const int tid  = threadIdx.x;
    const int lane = tid & 31;
    const int w    = tid >> 5;
    const int wm   = w & 1;               // 0..1  (M)
    const int wn   = w >> 1;              // 0..3  (N)
    const int m0   = blockIdx.y * 128;
    const int n0   = blockIdx.x * 128;

    int accm[4][4][4], accc[4][4][4];
#pragma unroll
    for (int i = 0; i < 4; i++)
#pragma unroll
        for (int j = 0; j < 4; j++)
#pragma unroll
            for (int c = 0; c < 4; c++) { accm[i][j][c] = 0; accc[i][j][c] = 0; }

    const int nk = K >> 7;                // 128-byte K-chunks
    load_chunk(A0, A1, B0, B1, m0, n0, K, 0, tid, sbase);

    // ldmatrix lane->address maps (identical to validated bf16 kernel)
    const int am   = wm * 64 + (lane & 15);                       // + mt*16
    const int acb  = (lane >> 4);                                 // 16B-half
    const int bn   = wn * 32 + (lane & 7) + ((lane >> 4) << 3);   // + bt*16
    const int bcb  = (lane >> 3) & 1;

    for (int i = 0; i < nk; i++) {
        if (i + 1 < nk) {
            load_chunk(A0, A1, B0, B1, m0, n0, K, (i + 1) << 7, tid,
                       sbase + (uint32_t)((i + 1) & 1) * STAGE);
            asm volatile("cp.async.wait_group 1;" ::: "memory");
        } else {
            asm volatile("cp.async.wait_group 0;" ::: "memory");
        }
        __syncthreads();

        const uint32_t sA  = sbase + (uint32_t)(i & 1) * STAGE;
        const uint32_t sAl = sA + 16384;
        const uint32_t sB  = sA + 32768;
        const uint32_t sBl = sA + 49152;

#pragma unroll
        for (int ks = 0; ks < 4; ks++) {          // each ks covers k=32 bytes
            uint32_t ahf[4][4], alf[4][4];
#pragma unroll
            for (int mt = 0; mt < 4; mt++) {
                int m = am + mt * 16;
                int c = ks * 2 + acb;
                uint32_t off = (uint32_t)(m * 128 + ((c ^ (m & 7)) << 4));
                ldsm_x4(ahf[mt], sA  + off);
                ldsm_x4(alf[mt], sAl + off);
            }
            uint32_t bhf[2][4], blf[2][4];
#pragma unroll
            for (int bt = 0; bt < 2; bt++) {
                int n = bn + bt * 16;
                int c = ks * 2 + bcb;
                uint32_t off = (uint32_t)(n * 128 + ((c ^ (n & 7)) << 4));
                ldsm_x4(bhf[bt], sB  + off);
                ldsm_x4(blf[bt], sBl + off);
            }
#pragma unroll
            for (int mt = 0; mt < 4; mt++)
#pragma unroll
                for (int nt = 0; nt < 4; nt++) {
                    const uint32_t* ph = &bhf[nt >> 1][(nt & 1) * 2];
                    const uint32_t* pl = &blf[nt >> 1][(nt & 1) * 2];
                    mma_s8(accm[mt][nt], ahf[mt], ph);
                    mma_s8(accc[mt][nt], ahf[mt], pl);
                    mma_s8(accc[mt][nt], alf[mt], ph);
                }
        }
        __syncthreads();
    }

    // ---- epilogue: c0=(g,2t) c1=(g,2t+1) c2=(g+8,2t) c3=(g+8,2t+1) ----
    const int gq = lane >> 2;
    const int tq = lane & 3;
    const float C254 = 1.0f / 254.0f;
#pragma unroll
    for (int mt = 0; mt < 4; mt++)
#pragma unroll
        for (int nt = 0; nt < 4; nt++) {
            const int n  = n0 + wn * 32 + nt * 8 + tq * 2;
            const float b0 = bias[n], b1 = bias[n + 1];
            const float sb0 = sb_[n], sb1 = sb_[n + 1];
#pragma unroll
            for (int half = 0; half < 2; half++) {
                const int m  = m0 + wm * 64 + mt * 16 + gq + half * 8;
                const float sam = sa[m];
                float v0 = sam * sb0 * ((float)accm[mt][nt][half * 2 + 0]
                         + (float)accc[mt][nt][half * 2 + 0] * C254) + b0;
                float v1 = sam * sb1 * ((float)accm[mt][nt][half * 2 + 1]
                         + (float)accc[mt][nt][half * 2 + 1] * C254) + b1;
                const size_t off = (size_t)m * N + n;
                if (EPI == 2) {
                    float2 r2 = *(const float2*)(res + off);
                    v0 += r2.x; v1 += r2.y;
                }
                if (EPI == 1) { v0 = fmaxf(v0, 0.0f); v1 = fmaxf(v1, 0.0f); }
                *(float2*)(Cf + off) = make_float2(v0, v1);
            }
        }
}

// ---------------------------------------------------------------------------
// Row quantization: one 128-thread block per row of length K (512 or 2048).
// x ~= s*(p0 + p1/254), s = rowmax/127 stored per row.
// ---------------------------------------------------------------------------
__global__ void __launch_bounds__(128)
rowquant(const float* __restrict__ x, int K,
         int8_t* __restrict__ p0, int8_t* __restrict__ p1,
         float* __restrict__ s)
{
    __shared__ float red[4];
    const int row = blockIdx.x;
    const int tid = threadIdx.x;
    const int lane = tid & 31, wid = tid >> 5;
    const int nv = K >> 9;                 // float4 iterations per thread
    const float* xr = x + (size_t)row * K;

    float4 v[4];
    float am = 0.0f;
#pragma unroll
    for (int j = 0; j < 4; j++) {
        if (j < nv) {
            v[j] = ((const float4*)xr)[tid + 128 * j];
            am = fmaxf(am, fmaxf(fmaxf(fabsf(v[j].x), fabsf(v[j].y)),
                                 fmaxf(fabsf(v[j].z), fabsf(v[j].w))));
        }
    }
#pragma unroll
    for (int o = 16; o > 0; o >>= 1)
        am = fmaxf(am, __shfl_xor_sync(0xffffffffu, am, o));
    if (lane == 0) red[wid] = am;
    __syncthreads();
    if (tid == 0)
        red[0] = fmaxf(fmaxf(red[0], red[1]), fmaxf(red[2], red[3]));
    __syncthreads();
    const float rmax = fmaxf(red[0], 1e-20f);
    const float sc   = rmax * (1.0f / 127.0f);
    const float inv  = 127.0f / rmax;
    if (tid == 0) s[row] = sc;

#pragma unroll
    for (int j = 0; j < 4; j++) {
        if (j < nv) {
            char4 c0, c1;
            float t, q;
            t = v[j].x * inv; q = rintf(t);
            c0.x = q_clamp((int)q); c1.x = q_clamp((int)rintf((t - q) * 254.0f));
            t = v[j].y * inv; q = rintf(t);
            c0.y = q_clamp((int)q); c1.y = q_clamp((int)rintf((t - q) * 254.0f));
            t = v[j].z * inv; q = rintf(t);
            c0.z = q_clamp((int)q); c1.z = q_clamp((int)rintf((t - q) * 254.0f));
            t = v[j].w * inv; q = rintf(t);
            c0.w = q_clamp((int)q); c1.w = q_clamp((int)rintf((t - q) * 254.0f));
            ((char4*)(p0 + (size_t)row * K))[tid + 128 * j] = c0;
            ((char4*)(p1 + (size_t)row * K))[tid + 128 * j] = c1;
        }
    }
}

// ---------------------------------------------------------------------------
// Windowed attention: grid (256 windows, 8 heads), 128 threads (1 q-row each).
// f32 in (qkv), f32 out.
// ---------------------------------------------------------------------------
#define KV_STR 65
#define S_STR  129
#define ATTN_SMEM_BYTES ((2 * 128 * KV_STR + 128 * S_STR) * (int)sizeof(float))

__global__ void __launch_bounds__(128)
attn_kernel(const float* __restrict__ qkv, float* __restrict__ out)
{
    extern __shared__ float sm[];
    float* Ks = sm;
    float* Vs = sm + 128 * KV_STR;
    float* Ss = sm + 2 * 128 * KV_STR;

    const int tid = threadIdx.x;
    const int win = blockIdx.x;
    const int h   = blockIdx.y;
    const size_t base = (size_t)win * 128 * D3 + h * 64;
    const float* kg = qkv + base + 512;
    const float* vg = qkv + base + 1024;

#pragma unroll
    for (int it = 0; it < 16; it++) {
        int idx = it * 128 + tid;
        int row = idx >> 4;
        int c   = (idx & 15) * 4;
        float4 kv = *(const float4*)(kg + (size_t)row * D3 + c);
        float4 vv = *(const float4*)(vg + (size_t)row * D3 + c);
        float* kd = Ks + row * KV_STR + c;
        kd[0] = kv.x; kd[1] = kv.y; kd[2] = kv.z; kd[3] = kv.w;
        float* vd = Vs + row * KV_STR + c;
        vd[0] = vv.x; vd[1] = vv.y; vd[2] = vv.z; vd[3] = vv.w;
    }

    float q[64];
    const float* qg = qkv + base + (size_t)tid * D3;
#pragma unroll
    for (int i = 0; i < 16; i++) {
        float4 v = *(const float4*)(qg + 4 * i);
        q[4*i] = v.x; q[4*i+1] = v.y; q[4*i+2] = v.z; q[4*i+3] = v.w;
    }
    __syncthreads();

    float* srow = Ss + tid * S_STR;
    float mx = -1e30f;
    for (int j = 0; j < 128; j++) {
        const float* kr = Ks + j * KV_STR;
        float s0 = 0.f, s1 = 0.f, s2 = 0.f, s3 = 0.f;
#pragma unroll
        for (int d = 0; d < 64; d += 4) {
            s0 += q[d]     * kr[d];
            s1 += q[d + 1] * kr[d + 1];
            s2 += q[d + 2] * kr[d + 2];
            s3 += q[d + 3] * kr[d + 3];
        }
        float s = (s0 + s1 + s2 + s3) * 0.125f;
        srow[j] = s;
        mx = fmaxf(mx, s);
    }
    float sum = 0.f;
    for (int j = 0; j < 128; j++) {
        float e = __expf(srow[j] - mx);
        srow[j] = e;
        sum += e;
    }
    const float inv = 1.0f / sum;

    float o[64];
#pragma unroll
    for (int d = 0; d < 64; d++) o[d] = 0.f;
    for (int j = 0; j < 128; j++) {
        float p = srow[j];
        const float* vr = Vs + j * KV_STR;
#pragma unroll
        for (int d = 0; d < 64; d++) o[d] += p * vr[d];
    }

    float* og = out + ((size_t)win * 128 + tid) * DD + h * 64;
#pragma unroll
    for (int i = 0; i < 16; i++)
        *(float4*)(og + 4 * i) = make_float4(o[4*i] * inv, o[4*i+1] * inv,
                                             o[4*i+2] * inv, o[4*i+3] * inv);
}

// ---------------------------------------------------------------------------
// LayerNorm over D=512 (1 row per 128-thread block).  QOUT=true also emits
// int8 2-plane quant + row scale for the following GEMM.
// ---------------------------------------------------------------------------
template <bool QOUT>
__global__ void __launch_bounds__(128)
ln_kernel(const float* __restrict__ x, const float* __restrict__ g,
          const float* __restrict__ b, float* __restrict__ outf,
          int8_t* __restrict__ p0, int8_t* __restrict__ p1,
          float* __restrict__ s)
{
    __shared__ float red[8];
    const int row = blockIdx.x;
    const int tid = threadIdx.x;
    const int lane = tid & 31, wid = tid >> 5;

    float4 v = *(const float4*)(x + (size_t)row * DD + tid * 4);
    float sm_ = v.x + v.y + v.z + v.w;
#pragma unroll
    for (int o = 16; o > 0; o >>= 1) sm_ += __shfl_xor_sync(0xffffffffu, sm_, o);
    if (lane == 0) red[wid] = sm_;
    __syncthreads();
    if (tid == 0) red[0] = red[0] + red[1] + red[2] + red[3];
    __syncthreads();
    const float mu = red[0] * (1.0f / 512.0f);

    const float d0 = v.x - mu, d1 = v.y - mu, d2 = v.z - mu, d3 = v.w - mu;
    float sq = d0*d0 + d1*d1 + d2*d2 + d3*d3;
#pragma unroll
    for (int o = 16; o > 0; o >>= 1) sq += __shfl_xor_sync(0xffffffffu, sq, o);
    __syncthreads();
    if (lane == 0) red[wid] = sq;
    __syncthreads();
    if (tid == 0) red[0] = red[0] + red[1] + red[2] + red[3];
    __syncthreads();
    const float inv = rsqrtf(red[0] * (1.0f / 512.0f) + 1e-5f);

    float4 gg = *(const float4*)(g + tid * 4);
    float4 bb = *(const float4*)(b + tid * 4);
    const float y0 = d0 * inv * gg.x + bb.x;
    const float y1 = d1 * inv * gg.y + bb.y;
    const float y2 = d2 * inv * gg.z + bb.z;
    const float y3 = d3 * inv * gg.w + bb.w;
    *(float4*)(outf + (size_t)row * DD + tid * 4) = make_float4(y0, y1, y2, y3);

    if (QOUT) {
        float am = fmaxf(fmaxf(fabsf(y0), fabsf(y1)), fmaxf(fabsf(y2), fabsf(y3)));
#pragma unroll
        for (int o = 16; o > 0; o >>= 1)
            am = fmaxf(am, __shfl_xor_sync(0xffffffffu, am, o));
        __syncthreads();
        if (lane == 0) red[wid] = am;
        __syncthreads();
        if (tid == 0)
            red[0] = fmaxf(fmaxf(red[0], red[1]), fmaxf(red[2], red[3]));
        __syncthreads();
        const float rmax = fmaxf(red[0], 1e-20f);
        const float sc   = rmax * (1.0f / 127.0f);
        const float qi   = 127.0f / rmax;
        if (tid == 0) s[row] = sc;
        char4 c0, c1;
        float t, qr;
        t = y0 * qi; qr = rintf(t);
        c0.x = q_clamp((int)qr); c1.x = q_clamp((int)rintf((t - qr) * 254.0f));
        t = y1 * qi; qr = rintf(t);
        c0.y = q_clamp((int)qr); c1.y = q_clamp((int)rintf((t - qr) * 254.0f));
        t = y2 * qi; qr = rintf(t);
        c0.z = q_clamp((int)qr); c1.z = q_clamp((int)rintf((t - qr) * 254.0f));
        t = y3 * qi; qr = rintf(t);
        c0.w = q_clamp((int)qr); c1.w = q_clamp((int)rintf((t - qr) * 254.0f));
        ((char4*)p0)[(size_t)row * 128 + tid] = c0;
        ((char4*)p1)[(size_t)row * 128 + tid] = c1;
    }
}

// ---------------------------------------------------------------------------
// Launch pipeline (graph-capturable)
// ---------------------------------------------------------------------------
extern "C" void kernel_launch(void* const* d_in, const int* in_sizes, int n_in,
                              void* d_out, int out_size)
{
    (void)in_sizes; (void)n_in; (void)out_size;
    const float* src  = (const float*)d_in[0];
    const float* wqkv = (const float*)d_in[1];
    const float* bqkv = (const float*)d_in[2];
    const float* wout = (const float*)d_in[3];
    const float* bout = (const float*)d_in[4];
    const float* ln1g = (const float*)d_in[5];
    const float* ln1b = (const float*)d_in[6];
    const float* w1   = (const float*)d_in[7];
    const float* b1   = (const float*)d_in[8];
    const float* w2   = (const float*)d_in[9];
    const float* b2   = (const float*)d_in[10];
    const float* ln2g = (const float*)d_in[11];
    const float* ln2b = (const float*)d_in[12];
    float* out = (float*)d_out;

    float *qkv, *attn, *x1, *resb, *ff;
    int8_t *sa0,*sa1,*at0,*at1,*xq0,*xq1,*fq0,*fq1;
    int8_t *q0,*q1,*o0,*o1,*u0,*u1,*dd0,*dd1;
    float *ssrc,*sattn,*sx,*sff,*swq,*swo,*sw1,*sw2;
    cudaGetSymbolAddress((void**)&qkv,  g_qkv);
    cudaGetSymbolAddress((void**)&attn, g_attn);
    cudaGetSymbolAddress((void**)&x1,   g_x1);
    cudaGetSymbolAddress((void**)&resb, g_resb);
    cudaGetSymbolAddress((void**)&ff,   g_ff);
    cudaGetSymbolAddress((void**)&sa0, g_sa0); cudaGetSymbolAddress((void**)&sa1, g_sa1);
    cudaGetSymbolAddress((void**)&at0, g_at0); cudaGetSymbolAddress((void**)&at1, g_at1);
    cudaGetSymbolAddress((void**)&xq0, g_xq0); cudaGetSymbolAddress((void**)&xq1, g_xq1);
    cudaGetSymbolAddress((void**)&fq0, g_fq0); cudaGetSymbolAddress((void**)&fq1, g_fq1);
    cudaGetSymbolAddress((void**)&q0,  g_q0);  cudaGetSymbolAddress((void**)&q1,  g_q1);
    cudaGetSymbolAddress((void**)&o0,  g_o0);  cudaGetSymbolAddress((void**)&o1,  g_o1);
    cudaGetSymbolAddress((void**)&u0,  g_u0);  cudaGetSymbolAddress((void**)&u1,  g_u1);
    cudaGetSymbolAddress((void**)&dd0, g_d0);  cudaGetSymbolAddress((void**)&dd1, g_d1);
    cudaGetSymbolAddress((void**)&ssrc, g_ssrc); cudaGetSymbolAddress((void**)&sattn, g_sattn);
    cudaGetSymbolAddress((void**)&sx,   g_sx);   cudaGetSymbolAddress((void**)&sff,   g_sff);
    cudaGetSymbolAddress((void**)&swq,  g_swq);  cudaGetSymbolAddress((void**)&swo,  g_swo);
    cudaGetSymbolAddress((void**)&sw1,  g_sw1);  cudaGetSymbolAddress((void**)&sw2,  g_sw2);

    const int GEMM_SMEM = 2 * STAGE + 1024;
    cudaFuncSetAttribute(tc_gemm<0>, cudaFuncAttributeMaxDynamicSharedMemorySize, GEMM_SMEM);
    cudaFuncSetAttribute(tc_gemm<1>, cudaFuncAttributeMaxDynamicSharedMemorySize, GEMM_SMEM);
    cudaFuncSetAttribute(tc_gemm<2>, cudaFuncAttributeMaxDynamicSharedMemorySize, GEMM_SMEM);
    cudaFuncSetAttribute(attn_kernel, cudaFuncAttributeMaxDynamicSharedMemorySize, ATTN_SMEM_BYTES);

    // 0) quantize inputs + weights (int8 2-plane, per-row scales)
    rowquant<<<MT, 128>>>(src,  DD, sa0, sa1, ssrc);
    rowquant<<<D3, 128>>>(wqkv, DD, q0,  q1,  swq);
    rowquant<<<DD, 128>>>(wout, DD, o0,  o1,  swo);
    rowquant<<<DF, 128>>>(w1,   DD, u0,  u1,  sw1);
    rowquant<<<DD, 128>>>(w2,   DF, dd0, dd1, sw2);

    // 1) QKV projection -> f32 qkv
    tc_gemm<0><<<dim3(D3 / 128, MT / 128), 256, GEMM_SMEM>>>(
        sa0, sa1, ssrc, q0, q1, swq, bqkv, nullptr, qkv, D3, DD);
    // 2) windowed attention -> f32 attn
    attn_kernel<<<dim3(MT / 128, 8), 128, ATTN_SMEM_BYTES>>>(qkv, attn);
    rowquant<<<MT, 128>>>(attn, DD, at0, at1, sattn);
    // 3) out projection + residual(src) -> resb
    tc_gemm<2><<<dim3(DD / 128, MT / 128), 256, GEMM_SMEM>>>(
        at0, at1, sattn, o0, o1, swo, bout, src, resb, DD, DD);
    // 4) LayerNorm 1 -> x1 f32 + int8 planes
    ln_kernel<true><<<MT, 128>>>(resb, ln1g, ln1b, x1, xq0, xq1, sx);
    // 5) FFN up + ReLU -> f32 ff, then quantize
    tc_gemm<1><<<dim3(DF / 128, MT / 128), 256, GEMM_SMEM>>>(
        xq0, xq1, sx, u0, u1, sw1, b1, nullptr, ff, DF, DD);
    rowquant<<<MT, 128>>>(ff, DF, fq0, fq1, sff);
    // 6) FFN down + residual(x1) -> resb
    tc_gemm<2><<<dim3(DD / 128, MT / 128), 256, GEMM_SMEM>>>(
        fq0, fq1, sff, dd0, dd1, sw2, b2, x1, resb, DD, DF);
    // 7) LayerNorm 2 -> output
    ln_kernel<false><<<MT, 128>>>(resb, ln2g, ln2b, out, nullptr, nullptr, nullptr);
}

// round 11
// speedup vs baseline: 2.8011x; 2.8011x over previous
#include <cuda_runtime.h>
#include <cuda_fp16.h>
#include <cstddef>
#include <cstdint>

// ---------------------------------------------------------------------------
// Problem constants: B=4, S=8192, D=512, H=8, HD=64, W=128.
// MT = 32768 tokens, 256 windows of 128.
// ---------------------------------------------------------------------------
#define MT 32768
#define DD 512
#define D3 1536
#define DF 2048

// ---------------------------------------------------------------------------
// Scratch (device globals — allocation-free per harness rules)
// ---------------------------------------------------------------------------
__device__ float g_qkv [(size_t)MT * D3];     // f32 qkv for attention
__device__ float g_x1  [(size_t)MT * DD];     // f32 ln1 output (FFN residual)
__device__ float g_resb[(size_t)MT * DD];     // f32 pre-LN buffer

// fp16 planes: activations hi/lo (A = Ah + Al, 22 bits), weights single plane
__device__ __half g_sh [(size_t)MT * DD], g_sl [(size_t)MT * DD];   // src
__device__ __half g_ah [(size_t)MT * DD], g_al [(size_t)MT * DD];   // attn out
__device__ __half g_xh [(size_t)MT * DD], g_xl [(size_t)MT * DD];   // ln1 out
__device__ __half g_fh [(size_t)MT * DF], g_fl [(size_t)MT * DF];   // ffn mid
__device__ __half g_wq [D3 * DD];
__device__ __half g_wo [DD * DD];
__device__ __half g_w1 [DF * DD];
__device__ __half g_w2 [DD * DF];

// ---------------------------------------------------------------------------
// PTX helpers (plain-compute_103 features: cp.async / ldmatrix / mma.sync)
// ---------------------------------------------------------------------------
__device__ __forceinline__ uint32_t cvta_s(const void* p) {
    uint32_t a;
    asm("{ .reg .u64 t; cvta.to.shared.u64 t, %1; cvt.u32.u64 %0, t; }"
        : "=r"(a) : "l"(p));
    return a;
}
__device__ __forceinline__ void cp16(uint32_t dst, const void* src) {
    asm volatile("cp.async.cg.shared.global [%0], [%1], 16;"
                 :: "r"(dst), "l"(src));
}
__device__ __forceinline__ void ldsm_x4(uint32_t* r, uint32_t addr) {
    asm volatile("ldmatrix.sync.aligned.m8n8.x4.shared.b16 {%0,%1,%2,%3}, [%4];"
                 : "=r"(r[0]), "=r"(r[1]), "=r"(r[2]), "=r"(r[3]) : "r"(addr));
}
__device__ __forceinline__ void mma_f16(float* d, const uint32_t* a,
                                        const uint32_t* b) {
    asm volatile(
        "mma.sync.aligned.m16n8k16.row.col.f32.f16.f16.f32 "
        "{%0,%1,%2,%3}, {%4,%5,%6,%7}, {%8,%9}, {%0,%1,%2,%3};"
        : "+f"(d[0]), "+f"(d[1]), "+f"(d[2]), "+f"(d[3])
        : "r"(a[0]), "r"(a[1]), "r"(a[2]), "r"(a[3]), "r"(b[0]), "r"(b[1]));
}

// fp32 -> (hi,lo) fp16 split, packed 2-wide into u32s
__device__ __forceinline__ void split2h(float a, float b, uint32_t& h, uint32_t& l) {
    __half ha = __float2half(a);
    __half hb = __float2half(b);
    __half la = __float2half(a - __half2float(ha));
    __half lb = __float2half(b - __half2float(hb));
    h = (uint32_t)__half_as_ushort(ha) | ((uint32_t)__half_as_ushort(hb) << 16);
    l = (uint32_t)__half_as_ushort(la) | ((uint32_t)__half_as_ushort(lb) << 16);
}

// ---------------------------------------------------------------------------
// HMMA fp16 2-pass GEMM: C[m,n] = sum_k A[m,k]*B[n,k] + bias[n] (+ epilogue)
//   A as hi/lo fp16 planes (exact to 2^-22), B single fp16 plane, both
//   K-major (non-trans ldmatrix for both operands — layout PROVEN in R9).
//   Both passes accumulate into ONE fp32 accumulator: C = (Ah+Al)*Bf.
//   CTA tile 128x128, BK=64 (128B rows, XOR-swizzled), 2-stage cp.async,
//   8 warps (2M x 4N), warp tile 64x32.
//   EPI 0: bias -> f32 out
//   EPI 1: bias + ReLU -> hi/lo fp16 planes
//   EPI 2: bias + f32 residual -> f32 out
// ---------------------------------------------------------------------------
static constexpr int STAGE = 49152;   // Ah 16K | Al 16K | B 16K

__device__ __forceinline__ void load_chunk(
    const __half* __restrict__ A0, const __half* __restrict__ A1,
    const __half* __restrict__ Bp,
    int m0, int n0, int K, int k0, int tid, uint32_t sb)
{
#pragma unroll
    for (int j = 0; j < 4; j++) {
        int id  = tid + 256 * j;          // 0..1023
        int row = id >> 3;                // 0..127
        int c   = id & 7;                 // 16B chunk within 128B row
        uint32_t soff = (uint32_t)(row * 128 + ((c ^ (row & 7)) << 4));
        size_t ga = (size_t)(m0 + row) * K + k0 + c * 8;
        size_t gb = (size_t)(n0 + row) * K + k0 + c * 8;
        cp16(sb + soff,          A0 + ga);
        cp16(sb + 16384 + soff,  A1 + ga);
        cp16(sb + 32768 + soff,  Bp + gb);
    }
    asm volatile("cp.async.commit_group;" ::: "memory");
}

template <int EPI>
__global__ void __launch_bounds__(256)
tc_gemm(const __half* __restrict__ A0, const __half* __restrict__ A1,
        const __half* __restrict__ Bp,
        const float* __restrict__ bias, const float* __restrict__ res,
        float* __restrict__ Cf,
        __half* __restrict__ Ch, __half* __restrict__ Cl,
        int N, int K)
{
    extern __shared__ __align__(1024) char dyn_smem[];
    uint32_t sbase = (cvta_s(dyn_smem) + 1023u) & ~1023u;

    const int tid  = threadIdx.x;
    const int lane = tid & 31;
    const int w    = tid >> 5;
    const int wm   = w & 1;               // 0..1  (M)
    const int wn   = w >> 1;              // 0..3  (N)
    const int m0   = blockIdx.y * 128;
    const int n0   = blockIdx.x * 128;

    float acc[4][4][4];
#pragma unroll
    for (int i = 0; i < 4; i++)
#pragma unroll
        for (int j = 0; j < 4; j++)
#pragma unroll
            for (int c = 0; c < 4; c++) acc[i][j][c] = 0.0f;

    const int nk = K >> 6;
    load_chunk(A0, A1, Bp, m0, n0, K, 0, tid, sbase);

    // ldmatrix lane->address maps (identical to validated R9 kernel)
    const int am   = wm * 64 + (lane & 15);                       // + mt*16
    const int acb  = (lane >> 4);                                 // k-half
    const int bn   = wn * 32 + (lane & 7) + ((lane >> 4) << 3);   // + bt*16
    const int bcb  = (lane >> 3) & 1;

    for (int i = 0; i < nk; i++) {
        if (i + 1 < nk) {
            load_chunk(A0, A1, Bp, m0, n0, K, (i + 1) << 6, tid,
                       sbase + (uint32_t)((i + 1) & 1) * STAGE);
            asm volatile("cp.async.wait_group 1;" ::: "memory");
        } else {
            asm volatile("cp.async.wait_group 0;" ::: "memory");
        }
        __syncthreads();

        const uint32_t sA  = sbase + (uint32_t)(i & 1) * STAGE;
        const uint32_t sAl = sA + 16384;
        const uint32_t sB  = sA + 32768;

#pragma unroll
        for (int ks = 0; ks < 4; ks++) {
            uint32_t ahf[4][4], alf[4][4];
#pragma unroll
            for (int mt = 0; mt < 4; mt++) {
                int m = am + mt * 16;
                int c = ks * 2 + acb;
                uint32_t off = (uint32_t)(m * 128 + ((c ^ (m & 7)) << 4));
                ldsm_x4(ahf[mt], sA  + off);
                ldsm_x4(alf[mt], sAl + off);
            }
            uint32_t bhf[2][4];
#pragma unroll
            for (int bt = 0; bt < 2; bt++) {
                int n = bn + bt * 16;
                int c = ks * 2 + bcb;
                uint32_t off = (uint32_t)(n * 128 + ((c ^ (n & 7)) << 4));
                ldsm_x4(bhf[bt], sB + off);     // non-trans: [n][k] == A layout
            }
#pragma unroll
            for (int mt = 0; mt < 4; mt++)
#pragma unroll
                for (int nt = 0; nt < 4; nt++) {
                    const uint32_t* pb = &bhf[nt >> 1][(nt & 1) * 2];
                    mma_f16(acc[mt][nt], ahf[mt], pb);   // Ah * B
                    mma_f16(acc[mt][nt], alf[mt], pb);   // Al * B (same acc)
                }
        }
        __syncthreads();
    }

    // ---- epilogue: c0=(g,2t) c1=(g,2t+1) c2=(g+8,2t) c3=(g+8,2t+1) ----
    const int gq = lane >> 2;
    const int tq = lane & 3;
#pragma unroll
    for (int mt = 0; mt < 4; mt++)
#pragma unroll
        for (int nt = 0; nt < 4; nt++) {
            const int n  = n0 + wn * 32 + nt * 8 + tq * 2;
            const float b0 = bias[n], b1 = bias[n + 1];
#pragma unroll
            for (int half = 0; half < 2; half++) {
                const int m  = m0 + wm * 64 + mt * 16 + gq + half * 8;
                float v0 = acc[mt][nt][half * 2 + 0] + b0;
                float v1 = acc[mt][nt][half * 2 + 1] + b1;
                const size_t off = (size_t)m * N + n;
                if (EPI == 2) {
                    float2 r2 = *(const float2*)(res + off);
                    v0 += r2.x; v1 += r2.y;
                }
                if (EPI == 1) {
                    v0 = fmaxf(v0, 0.0f); v1 = fmaxf(v1, 0.0f);
                    uint32_t hu, lu;
                    split2h(v0, v1, hu, lu);
                    *(uint32_t*)(Ch + off) = hu;
                    *(uint32_t*)(Cl + off) = lu;
                } else {
                    *(float2*)(Cf + off) = make_float2(v0, v1);
                }
            }
        }
}

// ---------------------------------------------------------------------------
// f32 -> hi/lo fp16 plane conversion (activations)
// ---------------------------------------------------------------------------
__global__ void __launch_bounds__(256)
cvt2_kernel(const float* __restrict__ x, __half* __restrict__ hi,
            __half* __restrict__ lo, int n4)
{
    int i = blockIdx.x * 256 + threadIdx.x;
    if (i >= n4) return;
    float4 v = ((const float4*)x)[i];
    uint32_t h0, l0, h1, l1;
    split2h(v.x, v.y, h0, l0);
    split2h(v.z, v.w, h1, l1);
    ((uint2*)hi)[i] = make_uint2(h0, h1);
    ((uint2*)lo)[i] = make_uint2(l0, l1);
}

// f32 -> single fp16 plane (weights)
__global__ void __launch_bounds__(256)
cvtw_kernel(const float* __restrict__ x, __half* __restrict__ hp, int n4)
{
    int i = blockIdx.x * 256 + threadIdx.x;
    if (i >= n4) return;
    float4 v = ((const float4*)x)[i];
    uint32_t a = (uint32_t)__half_as_ushort(__float2half(v.x))
               | ((uint32_t)__half_as_ushort(__float2half(v.y)) << 16);
    uint32_t b = (uint32_t)__half_as_ushort(__float2half(v.z))
               | ((uint32_t)__half_as_ushort(__float2half(v.w)) << 16);
    ((uint2*)hp)[i] = make_uint2(a, b);
}

// ---------------------------------------------------------------------------
// Windowed attention: grid (256 windows, 8 heads), 128 threads (1 q-row each).
// f32 math (unchanged, proven); writes hi/lo fp16 planes for next GEMM's A.
// ---------------------------------------------------------------------------
#define KV_STR 65
#define S_STR  129
#define ATTN_SMEM_BYTES ((2 * 128 * KV_STR + 128 * S_STR) * (int)sizeof(float))

__global__ void __launch_bounds__(128)
attn_kernel(const float* __restrict__ qkv,
            __half* __restrict__ oh, __half* __restrict__ ol)
{
    extern __shared__ float sm[];
    float* Ks = sm;
    float* Vs = sm + 128 * KV_STR;
    float* Ss = sm + 2 * 128 * KV_STR;

    const int tid = threadIdx.x;
    const int win = blockIdx.x;
    const int h   = blockIdx.y;
    const size_t base = (size_t)win * 128 * D3 + h * 64;
    const float* kg = qkv + base + 512;
    const float* vg = qkv + base + 1024;

#pragma unroll
    for (int it = 0; it < 16; it++) {
        int idx = it * 128 + tid;
        int row = idx >> 4;
        int c   = (idx & 15) * 4;
        float4 kv = *(const float4*)(kg + (size_t)row * D3 + c);
        float4 vv = *(const float4*)(vg + (size_t)row * D3 + c);
        float* kd = Ks + row * KV_STR + c;
        kd[0] = kv.x; kd[1] = kv.y; kd[2] = kv.z; kd[3] = kv.w;
        float* vd = Vs + row * KV_STR + c;
        vd[0] = vv.x; vd[1] = vv.y; vd[2] = vv.z; vd[3] = vv.w;
    }

    float q[64];
    const float* qg = qkv + base + (size_t)tid * D3;
#pragma unroll
    for (int i = 0; i < 16; i++) {
        float4 v = *(const float4*)(qg + 4 * i);
        q[4*i] = v.x; q[4*i+1] = v.y; q[4*i+2] = v.z; q[4*i+3] = v.w;
    }
    __syncthreads();

    float* srow = Ss + tid * S_STR;
    float mx = -1e30f;
    for (int j = 0; j < 128; j++) {
        const float* kr = Ks + j * KV_STR;
        float s0 = 0.f, s1 = 0.f, s2 = 0.f, s3 = 0.f;
#pragma unroll
        for (int d = 0; d < 64; d += 4) {
            s0 += q[d]     * kr[d];
            s1 += q[d + 1] * kr[d + 1];
            s2 += q[d + 2] * kr[d + 2];
            s3 += q[d + 3] * kr[d + 3];
        }
        float s = (s0 + s1 + s2 + s3) * 0.125f;
        srow[j] = s;
        mx = fmaxf(mx, s);
    }
    float sum = 0.f;
    for (int j = 0; j < 128; j++) {
        float e = __expf(srow[j] - mx);
        srow[j] = e;
        sum += e;
    }
    const float inv = 1.0f / sum;

    float o[64];
#pragma unroll
    for (int d = 0; d < 64; d++) o[d] = 0.f;
    for (int j = 0; j < 128; j++) {
        float p = srow[j];
        const float* vr = Vs + j * KV_STR;
#pragma unroll
        for (int d = 0; d < 64; d++) o[d] += p * vr[d];
    }

    const size_t ob = ((size_t)win * 128 + tid) * DD + h * 64;
#pragma unroll
    for (int qd = 0; qd < 16; qd++) {
        uint32_t h0, l0, h1, l1;
        split2h(o[4*qd]   * inv, o[4*qd+1] * inv, h0, l0);
        split2h(o[4*qd+2] * inv, o[4*qd+3] * inv, h1, l1);
        ((uint2*)(oh + ob))[qd] = make_uint2(h0, h1);
        ((uint2*)(ol + ob))[qd] = make_uint2(l0, l1);
    }
}

// ---------------------------------------------------------------------------
// LayerNorm over D=512 (1 row per 128-thread block).  HL=true also emits
// hi/lo fp16 planes for the following GEMM.
// ---------------------------------------------------------------------------
template <bool HL>
__global__ void __launch_bounds__(128)
ln_kernel(const float* __restrict__ x, const float* __restrict__ g,
          const float* __restrict__ b, float* __restrict__ outf,
          __half* __restrict__ oh, __half* __restrict__ ol)
{
    __shared__ float red[8];
    const int row = blockIdx.x;
    const int tid = threadIdx.x;
    const int lane = tid & 31, wid = tid >> 5;

    float4 v = *(const float4*)(x + (size_t)row * DD + tid * 4);
    float s = v.x + v.y + v.z + v.w;
#pragma unroll
    for (int o = 16; o > 0; o >>= 1) s += __shfl_xor_sync(0xffffffffu, s, o);
    if (lane == 0) red[wid] = s;
    __syncthreads();
    if (tid == 0) red[0] = red[0] + red[1] + red[2] + red[3];
    __syncthreads();
    const float mu = red[0] * (1.0f / 512.0f);

    const float d0 = v.x - mu, d1 = v.y - mu, d2 = v.z - mu, d3 = v.w - mu;
    float sq = d0*d0 + d1*d1 + d2*d2 + d3*d3;
#pragma unroll
    for (int o = 16; o > 0; o >>= 1) sq += __shfl_xor_sync(0xffffffffu, sq, o);
    __syncthreads();
    if (lane == 0) red[wid] = sq;
    __syncthreads();
    if (tid == 0) red[0] = red[0] + red[1] + red[2] + red[3];
    __syncthreads();
    const float inv = rsqrtf(red[0] * (1.0f / 512.0f) + 1e-5f);

    float4 gg = *(const float4*)(g + tid * 4);
    float4 bb = *(const float4*)(b + tid * 4);
    const float y0 = d0 * inv * gg.x + bb.x;
    const float y1 = d1 * inv * gg.y + bb.y;
    const float y2 = d2 * inv * gg.z + bb.z;
    const float y3 = d3 * inv * gg.w + bb.w;
    *(float4*)(outf + (size_t)row * DD + tid * 4) = make_float4(y0, y1, y2, y3);
    if (HL) {
        uint32_t h0, l0, h1, l1;
        split2h(y0, y1, h0, l0);
        split2h(y2, y3, h1, l1);
        const size_t i = (size_t)row * 128 + tid;
        ((uint2*)oh)[i] = make_uint2(h0, h1);
        ((uint2*)ol)[i] = make_uint2(l0, l1);
    }
}

// ---------------------------------------------------------------------------
// Launch pipeline (graph-capturable)
// ---------------------------------------------------------------------------
extern "C" void kernel_launch(void* const* d_in, const int* in_sizes, int n_in,
                              void* d_out, int out_size)
{
    (void)in_sizes; (void)n_in; (void)out_size;
    const float* src  = (const float*)d_in[0];
    const float* wqkv = (const float*)d_in[1];
    const float* bqkv = (const float*)d_in[2];
    const float* wout = (const float*)d_in[3];
    const float* bout = (const float*)d_in[4];
    const float* ln1g = (const float*)d_in[5];
    const float* ln1b = (const float*)d_in[6];
    const float* w1   = (const float*)d_in[7];
    const float* b1   = (const float*)d_in[8];
    const float* w2   = (const float*)d_in[9];
    const float* b2   = (const float*)d_in[10];
    const float* ln2g = (const float*)d_in[11];
    const float* ln2b = (const float*)d_in[12];
    float* out = (float*)d_out;

    float *qkv, *x1, *resb;
    __half *sh, *sl, *ah, *al, *xh, *xl, *fh, *fl;
    __half *wq, *wo, *wu, *wd;
    cudaGetSymbolAddress((void**)&qkv,  g_qkv);
    cudaGetSymbolAddress((void**)&x1,   g_x1);
    cudaGetSymbolAddress((void**)&resb, g_resb);
    cudaGetSymbolAddress((void**)&sh,  g_sh);  cudaGetSymbolAddress((void**)&sl,  g_sl);
    cudaGetSymbolAddress((void**)&ah,  g_ah);  cudaGetSymbolAddress((void**)&al,  g_al);
    cudaGetSymbolAddress((void**)&xh,  g_xh);  cudaGetSymbolAddress((void**)&xl,  g_xl);
    cudaGetSymbolAddress((void**)&fh,  g_fh);  cudaGetSymbolAddress((void**)&fl,  g_fl);
    cudaGetSymbolAddress((void**)&wq,  g_wq);  cudaGetSymbolAddress((void**)&wo,  g_wo);
    cudaGetSymbolAddress((void**)&wu,  g_w1);  cudaGetSymbolAddress((void**)&wd,  g_w2);

    const int GEMM_SMEM = 2 * STAGE + 1024;
    cudaFuncSetAttribute(tc_gemm<0>, cudaFuncAttributeMaxDynamicSharedMemorySize, GEMM_SMEM);
    cudaFuncSetAttribute(tc_gemm<1>, cudaFuncAttributeMaxDynamicSharedMemorySize, GEMM_SMEM);
    cudaFuncSetAttribute(tc_gemm<2>, cudaFuncAttributeMaxDynamicSharedMemorySize, GEMM_SMEM);
    cudaFuncSetAttribute(attn_kernel, cudaFuncAttributeMaxDynamicSharedMemorySize, ATTN_SMEM_BYTES);

    // 0) conversions: src -> hi/lo fp16; weights -> single fp16 plane
    cvt2_kernel<<<(MT * DD / 4 + 255) / 256, 256>>>(src,  sh, sl, MT * DD / 4);
    cvtw_kernel<<<(D3 * DD / 4 + 255) / 256, 256>>>(wqkv, wq, D3 * DD / 4);
    cvtw_kernel<<<(DD * DD / 4 + 255) / 256, 256>>>(wout, wo, DD * DD / 4);
    cvtw_kernel<<<(DF * DD / 4 + 255) / 256, 256>>>(w1,   wu, DF * DD / 4);
    cvtw_kernel<<<(DD * DF / 4 + 255) / 256, 256>>>(w2,   wd, DD * DF / 4);

    // 1) QKV projection -> f32 qkv
    tc_gemm<0><<<dim3(D3 / 128, MT / 128), 256, GEMM_SMEM>>>(
        sh, sl, wq, bqkv, nullptr, qkv, nullptr, nullptr, D3, DD);
    // 2) windowed attention -> attn hi/lo planes
    attn_kernel<<<dim3(MT / 128, 8), 128, ATTN_SMEM_BYTES>>>(qkv, ah, al);
    // 3) out projection + residual(src) -> resb f32
    tc_gemm<2><<<dim3(DD / 128, MT / 128), 256, GEMM_SMEM>>>(
        ah, al, wo, bout, src, resb, nullptr, nullptr, DD, DD);
    // 4) LayerNorm 1 -> x1 f32 + hi/lo planes
    ln_kernel<true><<<MT, 128>>>(resb, ln1g, ln1b, x1, xh, xl);
    // 5) FFN up + ReLU -> ff hi/lo planes
    tc_gemm<1><<<dim3(DF / 128, MT / 128), 256, GEMM_SMEM>>>(
        xh, xl, wu, b1, nullptr, nullptr, fh, fl, DF, DD);
    // 6) FFN down + residual(x1) -> resb f32
    tc_gemm<2><<<dim3(DD / 128, MT / 128), 256, GEMM_SMEM>>>(
        fh, fl, wd, b2, x1, resb, nullptr, nullptr, DD, DF);
    // 7) LayerNorm 2 -> output
    ln_kernel<false><<<MT, 128>>>(resb, ln2g, ln2b, out, nullptr, nullptr);
}

// round 13
// speedup vs baseline: 3.5751x; 1.2763x over previous
#include <cuda_runtime.h>
#include <cuda_fp16.h>
#include <cstddef>
#include <cstdint>

// ---------------------------------------------------------------------------
// Problem constants: B=4, S=8192, D=512, H=8, HD=64, W=128.
// MT = 32768 tokens, 256 windows of 128.
// ---------------------------------------------------------------------------
#define MT 32768
#define DD 512
#define D3 1536
#define DF 2048

// ---------------------------------------------------------------------------
// Scratch (device globals — allocation-free per harness rules)
// ---------------------------------------------------------------------------
__device__ float g_qkv [(size_t)MT * D3];     // f32 qkv for attention
__device__ float g_x1  [(size_t)MT * DD];     // f32 ln1 output (FFN residual)
__device__ float g_resb[(size_t)MT * DD];     // f32 pre-LN buffer

// single fp16 planes (1-pass GEMM operands; error calibrated vs R11 measurement)
__device__ __half g_sh [(size_t)MT * DD];   // src
__device__ __half g_ah [(size_t)MT * DD];   // attn out
__device__ __half g_xh [(size_t)MT * DD];   // ln1 out
__device__ __half g_fh [(size_t)MT * DF];   // ffn mid
__device__ __half g_wq [D3 * DD];
__device__ __half g_wo [DD * DD];
__device__ __half g_w1 [DF * DD];
__device__ __half g_w2 [DD * DF];

// ---------------------------------------------------------------------------
// PTX helpers (plain-compute_103 features: cp.async / ldmatrix / mma.sync)
// ---------------------------------------------------------------------------
__device__ __forceinline__ uint32_t cvta_s(const void* p) {
    uint32_t a;
    asm("{ .reg .u64 t; cvta.to.shared.u64 t, %1; cvt.u32.u64 %0, t; }"
        : "=r"(a) : "l"(p));
    return a;
}
__device__ __forceinline__ void cp16(uint32_t dst, const void* src) {
    asm volatile("cp.async.cg.shared.global [%0], [%1], 16;"
                 :: "r"(dst), "l"(src));
}
__device__ __forceinline__ void ldsm_x4(uint32_t* r, uint32_t addr) {
    asm volatile("ldmatrix.sync.aligned.m8n8.x4.shared.b16 {%0,%1,%2,%3}, [%4];"
                 : "=r"(r[0]), "=r"(r[1]), "=r"(r[2]), "=r"(r[3]) : "r"(addr));
}
__device__ __forceinline__ void mma_f16(float* d, const uint32_t* a,
                                        const uint32_t* b) {
    asm volatile(
        "mma.sync.aligned.m16n8k16.row.col.f32.f16.f16.f32 "
        "{%0,%1,%2,%3}, {%4,%5,%6,%7}, {%8,%9}, {%0,%1,%2,%3};"
        : "+f"(d[0]), "+f"(d[1]), "+f"(d[2]), "+f"(d[3])
        : "r"(a[0]), "r"(a[1]), "r"(a[2]), "r"(a[3]), "r"(b[0]), "r"(b[1]));
}

__device__ __forceinline__ uint32_t pack_h2(float a, float b) {
    return (uint32_t)__half_as_ushort(__float2half(a))
         | ((uint32_t)__half_as_ushort(__float2half(b)) << 16);
}

// ---------------------------------------------------------------------------
// HMMA fp16 1-pass GEMM: C[m,n] = sum_k A[m,k]*B[n,k] + bias[n] (+ epilogue)
//   A and B single fp16 planes, both K-major (non-trans ldmatrix for both —
//   layout PROVEN in R9/R11).  fp32 accumulate.
//   CTA tile 128x128, BK=64 (128B rows, XOR-swizzled), 2-stage cp.async,
//   8 warps (2M x 4N), warp tile 64x32.
//   EPI 0: bias -> f32 out
//   EPI 1: bias + ReLU -> fp16 plane
//   EPI 2: bias + f32 residual -> f32 out
// ---------------------------------------------------------------------------
static constexpr int STAGE = 32768;   // A 16K | B 16K

__device__ __forceinline__ void load_chunk(
    const __half* __restrict__ Ap, const __half* __restrict__ Bp,
    int m0, int n0, int K, int k0, int tid, uint32_t sb)
{
#pragma unroll
    for (int j = 0; j < 4; j++) {
        int id  = tid + 256 * j;          // 0..1023
        int row = id >> 3;                // 0..127
        int c   = id & 7;                 // 16B chunk within 128B row
        uint32_t soff = (uint32_t)(row * 128 + ((c ^ (row & 7)) << 4));
        size_t ga = (size_t)(m0 + row) * K + k0 + c * 8;
        size_t gb = (size_t)(n0 + row) * K + k0 + c * 8;
        cp16(sb + soff,          Ap + ga);
        cp16(sb + 16384 + soff,  Bp + gb);
    }
    asm volatile("cp.async.commit_group;" ::: "memory");
}

template <int EPI>
__global__ void __launch_bounds__(256)
tc_gemm(const __half* __restrict__ Ap, const __half* __restrict__ Bp,
        const float* __restrict__ bias, const float* __restrict__ res,
        float* __restrict__ Cf, __half* __restrict__ Ch,
        int N, int K)
{
    extern __shared__ __align__(1024) char dyn_smem[];
    uint32_t sbase = (cvta_s(dyn_smem) + 1023u) & ~1023u;

    const int tid  = threadIdx.x;
    const int lane = tid & 31;
    const int w    = tid >> 5;
    const int wm   = w & 1;               // 0..1  (M)
    const int wn   = w >> 1;              // 0..3  (N)
    const int m0   = blockIdx.y * 128;
    const int n0   = blockIdx.x * 128;

    float acc[4][4][4];
#pragma unroll
    for (int i = 0; i < 4; i++)
#pragma unroll
        for (int j = 0; j < 4; j++)
#pragma unroll
            for (int c = 0; c < 4; c++) acc[i][j][c] = 0.0f;

    const int nk = K >> 6;
    load_chunk(Ap, Bp, m0, n0, K, 0, tid, sbase);

    // ldmatrix lane->address maps (identical to validated R9/R11 kernels)
    const int am   = wm * 64 + (lane & 15);                       // + mt*16
    const int acb  = (lane >> 4);                                 // k-half
    const int bn   = wn * 32 + (lane & 7) + ((lane >> 4) << 3);   // + bt*16
    const int bcb  = (lane >> 3) & 1;

    for (int i = 0; i < nk; i++) {
        if (i + 1 < nk) {
            load_chunk(Ap, Bp, m0, n0, K, (i + 1) << 6, tid,
                       sbase + (uint32_t)((i + 1) & 1) * STAGE);
            asm volatile("cp.async.wait_group 1;" ::: "memory");
        } else {
            asm volatile("cp.async.wait_group 0;" ::: "memory");
        }
        __syncthreads();

        const uint32_t sA = sbase + (uint32_t)(i & 1) * STAGE;
        const uint32_t sB = sA + 16384;

#pragma unroll
        for (int ks = 0; ks < 4; ks++) {
            uint32_t ahf[4][4];
#pragma unroll
            for (int mt = 0; mt < 4; mt++) {
                int m = am + mt * 16;
                int c = ks * 2 + acb;
                uint32_t off = (uint32_t)(m * 128 + ((c ^ (m & 7)) << 4));
                ldsm_x4(ahf[mt], sA + off);
            }
            uint32_t bhf[2][4];
#pragma unroll
            for (int bt = 0; bt < 2; bt++) {
                int n = bn + bt * 16;
                int c = ks * 2 + bcb;
                uint32_t off = (uint32_t)(n * 128 + ((c ^ (n & 7)) << 4));
                ldsm_x4(bhf[bt], sB + off);     // non-trans: [n][k] == A layout
            }
#pragma unroll
            for (int mt = 0; mt < 4; mt++)
#pragma unroll
                for (int nt = 0; nt < 4; nt++)
                    mma_f16(acc[mt][nt], ahf[mt], &bhf[nt >> 1][(nt & 1) * 2]);
        }
        __syncthreads();
    }

    // ---- epilogue: c0=(g,2t) c1=(g,2t+1) c2=(g+8,2t) c3=(g+8,2t+1) ----
    const int gq = lane >> 2;
    const int tq = lane & 3;
#pragma unroll
    for (int mt = 0; mt < 4; mt++)
#pragma unroll
        for (int nt = 0; nt < 4; nt++) {
            const int n  = n0 + wn * 32 + nt * 8 + tq * 2;
            const float b0 = bias[n], b1 = bias[n + 1];
#pragma unroll
            for (int half = 0; half < 2; half++) {
                const int m  = m0 + wm * 64 + mt * 16 + gq + half * 8;
                float v0 = acc[mt][nt][half * 2 + 0] + b0;
                float v1 = acc[mt][nt][half * 2 + 1] + b1;
                const size_t off = (size_t)m * N + n;
                if (EPI == 2) {
                    float2 r2 = *(const float2*)(res + off);
                    v0 += r2.x; v1 += r2.y;
                }
                if (EPI == 1) {
                    v0 = fmaxf(v0, 0.0f); v1 = fmaxf(v1, 0.0f);
                    *(uint32_t*)(Ch + off) = pack_h2(v0, v1);
                } else {
                    *(float2*)(Cf + off) = make_float2(v0, v1);
                }
            }
        }
}

// ---------------------------------------------------------------------------
// f32 -> single fp16 plane conversion
// ---------------------------------------------------------------------------
__global__ void __launch_bounds__(256)
cvtw_kernel(const float* __restrict__ x, __half* __restrict__ hp, int n4)
{
    int i = blockIdx.x * 256 + threadIdx.x;
    if (i >= n4) return;
    float4 v = ((const float4*)x)[i];
    ((uint2*)hp)[i] = make_uint2(pack_h2(v.x, v.y), pack_h2(v.z, v.w));
}

// ---------------------------------------------------------------------------
// Windowed attention: grid (256 windows, 8 heads), 128 threads (1 q-row each).
// f32 math (unchanged, proven); writes single fp16 plane for next GEMM's A.
// ---------------------------------------------------------------------------
#define KV_STR 65
#define S_STR  129
#define ATTN_SMEM_BYTES ((2 * 128 * KV_STR + 128 * S_STR) * (int)sizeof(float))

__global__ void __launch_bounds__(128)
attn_kernel(const float* __restrict__ qkv, __half* __restrict__ oh)
{
    extern __shared__ float sm[];
    float* Ks = sm;
    float* Vs = sm + 128 * KV_STR;
    float* Ss = sm + 2 * 128 * KV_STR;

    const int tid = threadIdx.x;
    const int win = blockIdx.x;
    const int h   = blockIdx.y;
    const size_t base = (size_t)win * 128 * D3 + h * 64;
    const float* kg = qkv + base + 512;
    const float* vg = qkv + base + 1024;

#pragma unroll
    for (int it = 0; it < 16; it++) {
        int idx = it * 128 + tid;
        int row = idx >> 4;
        int c   = (idx & 15) * 4;
        float4 kv = *(const float4*)(kg + (size_t)row * D3 + c);
        float4 vv = *(const float4*)(vg + (size_t)row * D3 + c);
        float* kd = Ks + row * KV_STR + c;
        kd[0] = kv.x; kd[1] = kv.y; kd[2] = kv.z; kd[3] = kv.w;
        float* vd = Vs + row * KV_STR + c;
        vd[0] = vv.x; vd[1] = vv.y; vd[2] = vv.z; vd[3] = vv.w;
    }

    float q[64];
    const float* qg = qkv + base + (size_t)tid * D3;
#pragma unroll
    for (int i = 0; i < 16; i++) {
        float4 v = *(const float4*)(qg + 4 * i);
        q[4*i] = v.x; q[4*i+1] = v.y; q[4*i+2] = v.z; q[4*i+3] = v.w;
    }
    __syncthreads();

    float* srow = Ss + tid * S_STR;
    float mx = -1e30f;
    for (int j = 0; j < 128; j++) {
        const float* kr = Ks + j * KV_STR;
        float s0 = 0.f, s1 = 0.f, s2 = 0.f, s3 = 0.f;
#pragma unroll
        for (int d = 0; d < 64; d += 4) {
            s0 += q[d]     * kr[d];
            s1 += q[d + 1] * kr[d + 1];
            s2 += q[d + 2] * kr[d + 2];
            s3 += q[d + 3] * kr[d + 3];
        }
        float s = (s0 + s1 + s2 + s3) * 0.125f;
        srow[j] = s;
        mx = fmaxf(mx, s);
    }
    float sum = 0.f;
    for (int j = 0; j < 128; j++) {
        float e = __expf(srow[j] - mx);
        srow[j] = e;
        sum += e;
    }
    const float inv = 1.0f / sum;

    float o[64];
#pragma unroll
    for (int d = 0; d < 64; d++) o[d] = 0.f;
    for (int j = 0; j < 128; j++) {
        float p = srow[j];
        const float* vr = Vs + j * KV_STR;
#pragma unroll
        for (int d = 0; d < 64; d++) o[d] += p * vr[d];
    }

    // FIXED (R12 bug): write all 64 halfs with correct o[4*qd..4*qd+3] map.
    const size_t ob = ((size_t)win * 128 + tid) * DD + h * 64;
#pragma unroll
    for (int qd = 0; qd < 16; qd++) {
        ((uint2*)(oh + ob))[qd] =
            make_uint2(pack_h2(o[4*qd]     * inv, o[4*qd + 1] * inv),
                       pack_h2(o[4*qd + 2] * inv, o[4*qd + 3] * inv));
    }
}

// ---------------------------------------------------------------------------
// LayerNorm over D=512 (1 row per 128-thread block).  HL=true also emits a
// single fp16 plane for the following GEMM.
// ---------------------------------------------------------------------------
template <bool HL>
__global__ void __launch_bounds__(128)
ln_kernel(const float* __restrict__ x, const float* __restrict__ g,
          const float* __restrict__ b, float* __restrict__ outf,
          __half* __restrict__ oh)
{
    __shared__ float red[8];
    const int row = blockIdx.x;
    const int tid = threadIdx.x;
    const int lane = tid & 31, wid = tid >> 5;

    float4 v = *(const float4*)(x + (size_t)row * DD + tid * 4);
    float s = v.x + v.y + v.z + v.w;
#pragma unroll
    for (int o = 16; o > 0; o >>= 1) s += __shfl_xor_sync(0xffffffffu, s, o);
    if (lane == 0) red[wid] = s;
    __syncthreads();
    if (tid == 0) red[0] = red[0] + red[1] + red[2] + red[3];
    __syncthreads();
    const float mu = red[0] * (1.0f / 512.0f);

    const float d0 = v.x - mu, d1 = v.y - mu, d2 = v.z - mu, d3 = v.w - mu;
    float sq = d0*d0 + d1*d1 + d2*d2 + d3*d3;
#pragma unroll
    for (int o = 16; o > 0; o >>= 1) sq += __shfl_xor_sync(0xffffffffu, sq, o);
    __syncthreads();
    if (lane == 0) red[wid] = sq;
    __syncthreads();
    if (tid == 0) red[0] = red[0] + red[1] + red[2] + red[3];
    __syncthreads();
    const float inv = rsqrtf(red[0] * (1.0f / 512.0f) + 1e-5f);

    float4 gg = *(const float4*)(g + tid * 4);
    float4 bb = *(const float4*)(b + tid * 4);
    const float y0 = d0 * inv * gg.x + bb.x;
    const float y1 = d1 * inv * gg.y + bb.y;
    const float y2 = d2 * inv * gg.z + bb.z;
    const float y3 = d3 * inv * gg.w + bb.w;
    *(float4*)(outf + (size_t)row * DD + tid * 4) = make_float4(y0, y1, y2, y3);
    if (HL) {
        const size_t i = (size_t)row * 128 + tid;
        ((uint2*)oh)[i] = make_uint2(pack_h2(y0, y1), pack_h2(y2, y3));
    }
}

// ---------------------------------------------------------------------------
// Launch pipeline (graph-capturable)
// ---------------------------------------------------------------------------
extern "C" void kernel_launch(void* const* d_in, const int* in_sizes, int n_in,
                              void* d_out, int out_size)
{
    (void)in_sizes; (void)n_in; (void)out_size;
    const float* src  = (const float*)d_in[0];
    const float* wqkv = (const float*)d_in[1];
    const float* bqkv = (const float*)d_in[2];
    const float* wout = (const float*)d_in[3];
    const float* bout = (const float*)d_in[4];
    const float* ln1g = (const float*)d_in[5];
    const float* ln1b = (const float*)d_in[6];
    const float* w1   = (const float*)d_in[7];
    const float* b1   = (const float*)d_in[8];
    const float* w2   = (const float*)d_in[9];
    const float* b2   = (const float*)d_in[10];
    const float* ln2g = (const float*)d_in[11];
    const float* ln2b = (const float*)d_in[12];
    float* out = (float*)d_out;

    float *qkv, *x1, *resb;
    __half *sh, *ah, *xh, *fh, *wq, *wo, *wu, *wd;
    cudaGetSymbolAddress((void**)&qkv,  g_qkv);
    cudaGetSymbolAddress((void**)&x1,   g_x1);
    cudaGetSymbolAddress((void**)&resb, g_resb);
    cudaGetSymbolAddress((void**)&sh,  g_sh);
    cudaGetSymbolAddress((void**)&ah,  g_ah);
    cudaGetSymbolAddress((void**)&xh,  g_xh);
    cudaGetSymbolAddress((void**)&fh,  g_fh);
    cudaGetSymbolAddress((void**)&wq,  g_wq);  cudaGetSymbolAddress((void**)&wo,  g_wo);
    cudaGetSymbolAddress((void**)&wu,  g_w1);  cudaGetSymbolAddress((void**)&wd,  g_w2);

    const int GEMM_SMEM = 2 * STAGE + 1024;
    cudaFuncSetAttribute(tc_gemm<0>, cudaFuncAttributeMaxDynamicSharedMemorySize, GEMM_SMEM);
    cudaFuncSetAttribute(tc_gemm<1>, cudaFuncAttributeMaxDynamicSharedMemorySize, GEMM_SMEM);
    cudaFuncSetAttribute(tc_gemm<2>, cudaFuncAttributeMaxDynamicSharedMemorySize, GEMM_SMEM);
    cudaFuncSetAttribute(attn_kernel, cudaFuncAttributeMaxDynamicSharedMemorySize, ATTN_SMEM_BYTES);

    // 0) conversions: everything -> single fp16 plane
    cvtw_kernel<<<(MT * DD / 4 + 255) / 256, 256>>>(src,  sh, MT * DD / 4);
    cvtw_kernel<<<(D3 * DD / 4 + 255) / 256, 256>>>(wqkv, wq, D3 * DD / 4);
    cvtw_kernel<<<(DD * DD / 4 + 255) / 256, 256>>>(wout, wo, DD * DD / 4);
    cvtw_kernel<<<(DF * DD / 4 + 255) / 256, 256>>>(w1,   wu, DF * DD / 4);
    cvtw_kernel<<<(DD * DF / 4 + 255) / 256, 256>>>(w2,   wd, DD * DF / 4);

    // 1) QKV projection -> f32 qkv
    tc_gemm<0><<<dim3(D3 / 128, MT / 128), 256, GEMM_SMEM>>>(
        sh, wq, bqkv, nullptr, qkv, nullptr, D3, DD);
    // 2) windowed attention -> attn fp16 plane
    attn_kernel<<<dim3(MT / 128, 8), 128, ATTN_SMEM_BYTES>>>(qkv, ah);
    // 3) out projection + residual(src) -> resb f32
    tc_gemm<2><<<dim3(DD / 128, MT / 128), 256, GEMM_SMEM>>>(
        ah, wo, bout, src, resb, nullptr, DD, DD);
    // 4) LayerNorm 1 -> x1 f32 + fp16 plane
    ln_kernel<true><<<MT, 128>>>(resb, ln1g, ln1b, x1, xh);
    // 5) FFN up + ReLU -> ff fp16 plane
    tc_gemm<1><<<dim3(DF / 128, MT / 128), 256, GEMM_SMEM>>>(
        xh, wu, b1, nullptr, nullptr, fh, DF, DD);
    // 6) FFN down + residual(x1) -> resb f32
    tc_gemm<2><<<dim3(DD / 128, MT / 128), 256, GEMM_SMEM>>>(
        fh, wd, b2, x1, resb, nullptr, DD, DF);
    // 7) LayerNorm 2 -> output
    ln_kernel<false><<<MT, 128>>>(resb, ln2g, ln2b, out, nullptr);
}

// round 14
// speedup vs baseline: 8.3418x; 2.3333x over previous
#include <cuda_runtime.h>
#include <cuda_fp16.h>
#include <cstddef>
#include <cstdint>

// ---------------------------------------------------------------------------
// Problem constants: B=4, S=8192, D=512, H=8, HD=64, W=128.
// MT = 32768 tokens, 256 windows of 128.
// ---------------------------------------------------------------------------
#define MT 32768
#define DD 512
#define D3 1536
#define DF 2048

// ---------------------------------------------------------------------------
// Scratch (device globals — allocation-free per harness rules)
// ---------------------------------------------------------------------------
__device__ float g_x1  [(size_t)MT * DD];     // f32 ln1 output (FFN residual)
__device__ float g_resb[(size_t)MT * DD];     // f32 pre-LN buffer

// fp16 planes
__device__ __half g_qh [(size_t)MT * D3];   // qkv (fp16, QKV-GEMM output)
__device__ __half g_sh [(size_t)MT * DD];   // src
__device__ __half g_ah [(size_t)MT * DD];   // attn out
__device__ __half g_xh [(size_t)MT * DD];   // ln1 out
__device__ __half g_fh [(size_t)MT * DF];   // ffn mid
__device__ __half g_wq [D3 * DD];
__device__ __half g_wo [DD * DD];
__device__ __half g_w1 [DF * DD];
__device__ __half g_w2 [DD * DF];

// ---------------------------------------------------------------------------
// PTX helpers (plain-compute_103 features: cp.async / ldmatrix / mma.sync)
// ---------------------------------------------------------------------------
__device__ __forceinline__ uint32_t cvta_s(const void* p) {
    uint32_t a;
    asm("{ .reg .u64 t; cvta.to.shared.u64 t, %1; cvt.u32.u64 %0, t; }"
        : "=r"(a) : "l"(p));
    return a;
}
__device__ __forceinline__ void cp16(uint32_t dst, const void* src) {
    asm volatile("cp.async.cg.shared.global [%0], [%1], 16;"
                 :: "r"(dst), "l"(src));
}
__device__ __forceinline__ void ldsm_x4(uint32_t* r, uint32_t addr) {
    asm volatile("ldmatrix.sync.aligned.m8n8.x4.shared.b16 {%0,%1,%2,%3}, [%4];"
                 : "=r"(r[0]), "=r"(r[1]), "=r"(r[2]), "=r"(r[3]) : "r"(addr));
}
__device__ __forceinline__ void mma_f16(float* d, const uint32_t* a,
                                        const uint32_t* b) {
    asm volatile(
        "mma.sync.aligned.m16n8k16.row.col.f32.f16.f16.f32 "
        "{%0,%1,%2,%3}, {%4,%5,%6,%7}, {%8,%9}, {%0,%1,%2,%3};"
        : "+f"(d[0]), "+f"(d[1]), "+f"(d[2]), "+f"(d[3])
        : "r"(a[0]), "r"(a[1]), "r"(a[2]), "r"(a[3]), "r"(b[0]), "r"(b[1]));
}

__device__ __forceinline__ uint32_t pack_h2(float a, float b) {
    return (uint32_t)__half_as_ushort(__float2half(a))
         | ((uint32_t)__half_as_ushort(__float2half(b)) << 16);
}

// ---------------------------------------------------------------------------
// HMMA fp16 1-pass GEMM (PROVEN R13): C = A*B^T + bias (+ epilogue)
//   EPI 0: bias -> f32    EPI 1: bias+ReLU -> fp16   EPI 2: bias+res -> f32
//   EPI 3: bias -> fp16   (for QKV output)
// ---------------------------------------------------------------------------
static constexpr int STAGE = 32768;   // A 16K | B 16K

__device__ __forceinline__ void load_chunk(
    const __half* __restrict__ Ap, const __half* __restrict__ Bp,
    int m0, int n0, int K, int k0, int tid, uint32_t sb)
{
#pragma unroll
    for (int j = 0; j < 4; j++) {
        int id  = tid + 256 * j;          // 0..1023
        int row = id >> 3;                // 0..127
        int c   = id & 7;                 // 16B chunk within 128B row
        uint32_t soff = (uint32_t)(row * 128 + ((c ^ (row & 7)) << 4));
        size_t ga = (size_t)(m0 + row) * K + k0 + c * 8;
        size_t gb = (size_t)(n0 + row) * K + k0 + c * 8;
        cp16(sb + soff,          Ap + ga);
        cp16(sb + 16384 + soff,  Bp + gb);
    }
    asm volatile("cp.async.commit_group;" ::: "memory");
}

template <int EPI>
__global__ void __launch_bounds__(256)
tc_gemm(const __half* __restrict__ Ap, const __half* __restrict__ Bp,
        const float* __restrict__ bias, const float* __restrict__ res,
        float* __restrict__ Cf, __half* __restrict__ Ch,
        int N, int K)
{
    extern __shared__ __align__(1024) char dyn_smem[];
    uint32_t sbase = (cvta_s(dyn_smem) + 1023u) & ~1023u;

    const int tid  = threadIdx.x;
    const int lane = tid & 31;
    const int w    = tid >> 5;
    const int wm   = w & 1;               // 0..1  (M)
    const int wn   = w >> 1;              // 0..3  (N)
    const int m0   = blockIdx.y * 128;
    const int n0   = blockIdx.x * 128;

    float acc[4][4][4];
#pragma unroll
    for (int i = 0; i < 4; i++)
#pragma unroll
        for (int j = 0; j < 4; j++)
#pragma unroll
            for (int c = 0; c < 4; c++) acc[i][j][c] = 0.0f;

    const int nk = K >> 6;
    load_chunk(Ap, Bp, m0, n0, K, 0, tid, sbase);

    const int am   = wm * 64 + (lane & 15);                       // + mt*16
    const int acb  = (lane >> 4);                                 // k-half
    const int bn   = wn * 32 + (lane & 7) + ((lane >> 4) << 3);   // + bt*16
    const int bcb  = (lane >> 3) & 1;

    for (int i = 0; i < nk; i++) {
        if (i + 1 < nk) {
            load_chunk(Ap, Bp, m0, n0, K, (i + 1) << 6, tid,
                       sbase + (uint32_t)((i + 1) & 1) * STAGE);
            asm volatile("cp.async.wait_group 1;" ::: "memory");
        } else {
            asm volatile("cp.async.wait_group 0;" ::: "memory");
        }
        __syncthreads();

        const uint32_t sA = sbase + (uint32_t)(i & 1) * STAGE;
        const uint32_t sB = sA + 16384;

#pragma unroll
        for (int ks = 0; ks < 4; ks++) {
            uint32_t ahf[4][4];
#pragma unroll
            for (int mt = 0; mt < 4; mt++) {
                int m = am + mt * 16;
                int c = ks * 2 + acb;
                uint32_t off = (uint32_t)(m * 128 + ((c ^ (m & 7)) << 4));
                ldsm_x4(ahf[mt], sA + off);
            }
            uint32_t bhf[2][4];
#pragma unroll
            for (int bt = 0; bt < 2; bt++) {
                int n = bn + bt * 16;
                int c = ks * 2 + bcb;
                uint32_t off = (uint32_t)(n * 128 + ((c ^ (n & 7)) << 4));
                ldsm_x4(bhf[bt], sB + off);     // non-trans: [n][k] == A layout
            }
#pragma unroll
            for (int mt = 0; mt < 4; mt++)
#pragma unroll
                for (int nt = 0; nt < 4; nt++)
                    mma_f16(acc[mt][nt], ahf[mt], &bhf[nt >> 1][(nt & 1) * 2]);
        }
        __syncthreads();
    }

    // ---- epilogue: c0=(g,2t) c1=(g,2t+1) c2=(g+8,2t) c3=(g+8,2t+1) ----
    const int gq = lane >> 2;
    const int tq = lane & 3;
#pragma unroll
    for (int mt = 0; mt < 4; mt++)
#pragma unroll
        for (int nt = 0; nt < 4; nt++) {
            const int n  = n0 + wn * 32 + nt * 8 + tq * 2;
            const float b0 = bias[n], b1 = bias[n + 1];
#pragma unroll
            for (int half = 0; half < 2; half++) {
                const int m  = m0 + wm * 64 + mt * 16 + gq + half * 8;
                float v0 = acc[mt][nt][half * 2 + 0] + b0;
                float v1 = acc[mt][nt][half * 2 + 1] + b1;
                const size_t off = (size_t)m * N + n;
                if (EPI == 2) {
                    float2 r2 = *(const float2*)(res + off);
                    v0 += r2.x; v1 += r2.y;
                }
                if (EPI == 1) {
                    v0 = fmaxf(v0, 0.0f); v1 = fmaxf(v1, 0.0f);
                    *(uint32_t*)(Ch + off) = pack_h2(v0, v1);
                } else if (EPI == 3) {
                    *(uint32_t*)(Ch + off) = pack_h2(v0, v1);
                } else {
                    *(float2*)(Cf + off) = make_float2(v0, v1);
                }
            }
        }
}

// ---------------------------------------------------------------------------
// f32 -> single fp16 plane conversion
// ---------------------------------------------------------------------------
__global__ void __launch_bounds__(256)
cvtw_kernel(const float* __restrict__ x, __half* __restrict__ hp, int n4)
{
    int i = blockIdx.x * 256 + threadIdx.x;
    if (i >= n4) return;
    float4 v = ((const float4*)x)[i];
    ((uint2*)hp)[i] = make_uint2(pack_h2(v.x, v.y), pack_h2(v.z, v.w));
}

// ---------------------------------------------------------------------------
// HMMA windowed attention. Grid (256 windows, 8 heads), 256 threads (8 warps,
// 16 query rows each). fp16 qkv in, fp16 attn out.
//   S-phase: Q (A-op) and K (B-op) use the PROVEN GEMM ldmatrix addressing
//            ([row][k] tiles, 128B rows, XOR swizzle).
//   Softmax: full 128-wide rows live in warp registers; 2 shfl-xor reductions.
//   PV-phase: P packed from S fragments (register algebra per PTX frag spec);
//            V transposed once into Vt[n][k] (272B row stride -> the 8
//            ldmatrix addresses differ by 16B mod 128B: conflict-free),
//            then the PROVEN non-trans B path applies.
// ---------------------------------------------------------------------------
#define VT_STR 272
#define ATT_SMEM (32768 + 64 * VT_STR)   // Q 16K | K 16K | Vt 17KB

__global__ void __launch_bounds__(256)
attn_kernel(const __half* __restrict__ qkv, __half* __restrict__ oh)
{
    extern __shared__ __align__(1024) char asmem[];
    const uint32_t sb = cvta_s(asmem);
    const uint32_t Qs = sb, Ks = sb + 16384, Vt = sb + 32768;

    const int tid  = threadIdx.x;
    const int lane = tid & 31;
    const int w    = tid >> 5;
    const int win  = blockIdx.x;
    const int h    = blockIdx.y;
    const size_t tb = (size_t)win * 128 * D3 + h * 64;   // half-element base

    // Q,K cooperative cp.async loads (swizzled 128B rows)
#pragma unroll
    for (int it = 0; it < 4; it++) {
        int u = it * 256 + tid;          // 0..1023
        int row = u >> 3, c = u & 7;
        uint32_t soff = (uint32_t)(row * 128 + ((c ^ (row & 7)) << 4));
        const __half* qg = qkv + tb + (size_t)row * D3 + c * 8;
        cp16(Qs + soff, qg);
        cp16(Ks + soff, qg + 512);
    }
    asm volatile("cp.async.commit_group;" ::: "memory");

    // V transpose into Vt[n][k]: coalesced uint2 reads, scalar half stores
#pragma unroll
    for (int it = 0; it < 8; it++) {
        int u = it * 256 + tid;          // 0..2047 uint2 units
        int k = u >> 4, nq = (u & 15) << 2;
        uint2 vv = *(const uint2*)(qkv + tb + (size_t)k * D3 + 1024 + nq);
        const __half* hp = (const __half*)&vv;
#pragma unroll
        for (int j = 0; j < 4; j++)
            *(__half*)(asmem + 32768 + (nq + j) * VT_STR + k * 2) = hp[j];
    }
    asm volatile("cp.async.wait_group 0;" ::: "memory");
    __syncthreads();

    // ---- S = Q K^T : warp w owns rows w*16..w*16+15, all 128 cols ----
    float s[16][4];
#pragma unroll
    for (int t = 0; t < 16; t++)
#pragma unroll
        for (int c = 0; c < 4; c++) s[t][c] = 0.0f;

    const int am  = w * 16 + (lane & 15);
    const int acb = lane >> 4;
    const int bn8 = (lane & 7) + ((lane >> 4) << 3);
    const int bcb = (lane >> 3) & 1;

#pragma unroll
    for (int ks = 0; ks < 4; ks++) {          // k = 64 head dim
        uint32_t a[4];
        {
            int c = ks * 2 + acb;
            ldsm_x4(a, Qs + (uint32_t)(am * 128 + ((c ^ (am & 7)) << 4)));
        }
#pragma unroll
        for (int jp = 0; jp < 8; jp++) {      // 16 cols per iter
            uint32_t b[4];
            int n = jp * 16 + bn8;
            int c = ks * 2 + bcb;
            ldsm_x4(b, Ks + (uint32_t)(n * 128 + ((c ^ (n & 7)) << 4)));
            mma_f16(s[2 * jp],     a, b);
            mma_f16(s[2 * jp + 1], a, b + 2);
        }
    }

    // ---- softmax over 128 cols (scale 1/8 folded into exp) ----
    float m0 = -1e30f, m1 = -1e30f;
#pragma unroll
    for (int t = 0; t < 16; t++) {
        m0 = fmaxf(m0, fmaxf(s[t][0], s[t][1]));
        m1 = fmaxf(m1, fmaxf(s[t][2], s[t][3]));
    }
    m0 = fmaxf(m0, __shfl_xor_sync(0xffffffffu, m0, 1));
    m0 = fmaxf(m0, __shfl_xor_sync(0xffffffffu, m0, 2));
    m1 = fmaxf(m1, __shfl_xor_sync(0xffffffffu, m1, 1));
    m1 = fmaxf(m1, __shfl_xor_sync(0xffffffffu, m1, 2));

    float sum0 = 0.0f, sum1 = 0.0f;
#pragma unroll
    for (int t = 0; t < 16; t++) {
        s[t][0] = __expf((s[t][0] - m0) * 0.125f); sum0 += s[t][0];
        s[t][1] = __expf((s[t][1] - m0) * 0.125f); sum0 += s[t][1];
        s[t][2] = __expf((s[t][2] - m1) * 0.125f); sum1 += s[t][2];
        s[t][3] = __expf((s[t][3] - m1) * 0.125f); sum1 += s[t][3];
    }
    sum0 += __shfl_xor_sync(0xffffffffu, sum0, 1);
    sum0 += __shfl_xor_sync(0xffffffffu, sum0, 2);
    sum1 += __shfl_xor_sync(0xffffffffu, sum1, 1);
    sum1 += __shfl_xor_sync(0xffffffffu, sum1, 2);
    const float inv0 = 1.0f / sum0, inv1 = 1.0f / sum1;
#pragma unroll
    for (int t = 0; t < 16; t++) {
        s[t][0] *= inv0; s[t][1] *= inv0;
        s[t][2] *= inv1; s[t][3] *= inv1;
    }

    // ---- O = P V : P fragments from S registers, V via Vt non-trans ----
    float o[8][4];
#pragma unroll
    for (int t = 0; t < 8; t++)
#pragma unroll
        for (int c = 0; c < 4; c++) o[t][c] = 0.0f;

#pragma unroll
    for (int kc = 0; kc < 8; kc++) {          // k = 128 window positions
        uint32_t a[4];
        a[0] = pack_h2(s[2 * kc][0],     s[2 * kc][1]);
        a[1] = pack_h2(s[2 * kc][2],     s[2 * kc][3]);
        a[2] = pack_h2(s[2 * kc + 1][0], s[2 * kc + 1][1]);
        a[3] = pack_h2(s[2 * kc + 1][2], s[2 * kc + 1][3]);
#pragma unroll
        for (int bp = 0; bp < 4; bp++) {      // 16 of 64 out-cols per iter
            uint32_t b[4];
            int n = bp * 16 + bn8;
            int c = kc * 2 + bcb;             // 16B units within 256B Vt row
            ldsm_x4(b, Vt + (uint32_t)(n * VT_STR + c * 16));
            mma_f16(o[2 * bp],     a, b);
            mma_f16(o[2 * bp + 1], a, b + 2);
        }
    }

    // ---- store fp16 attn output ----
    const int gq = lane >> 2, tq = lane & 3;
#pragma unroll
    for (int nt = 0; nt < 8; nt++) {
        const int n = nt * 8 + tq * 2;
#pragma unroll
        for (int half = 0; half < 2; half++) {
            const int row = w * 16 + gq + half * 8;
            const size_t off = ((size_t)win * 128 + row) * DD + h * 64 + n;
            *(uint32_t*)(oh + off) = pack_h2(o[nt][half * 2], o[nt][half * 2 + 1]);
        }
    }
}

// ---------------------------------------------------------------------------
// LayerNorm over D=512 (1 row per 128-thread block).  HL=true also emits a
// single fp16 plane for the following GEMM.
// ---------------------------------------------------------------------------
template <bool HL>
__global__ void __launch_bounds__(128)
ln_kernel(const float* __restrict__ x, const float* __restrict__ g,
          const float* __restrict__ b, float* __restrict__ outf,
          __half* __restrict__ oh)
{
    __shared__ float red[8];
    const int row = blockIdx.x;
    const int tid = threadIdx.x;
    const int lane = tid & 31, wid = tid >> 5;

    float4 v = *(const float4*)(x + (size_t)row * DD + tid * 4);
    float s = v.x + v.y + v.z + v.w;
#pragma unroll
    for (int o = 16; o > 0; o >>= 1) s += __shfl_xor_sync(0xffffffffu, s, o);
    if (lane == 0) red[wid] = s;
    __syncthreads();
    if (tid == 0) red[0] = red[0] + red[1] + red[2] + red[3];
    __syncthreads();
    const float mu = red[0] * (1.0f / 512.0f);

    const float d0 = v.x - mu, d1 = v.y - mu, d2 = v.z - mu, d3 = v.w - mu;
    float sq = d0*d0 + d1*d1 + d2*d2 + d3*d3;
#pragma unroll
    for (int o = 16; o > 0; o >>= 1) sq += __shfl_xor_sync(0xffffffffu, sq, o);
    __syncthreads();
    if (lane == 0) red[wid] = sq;
    __syncthreads();
    if (tid == 0) red[0] = red[0] + red[1] + red[2] + red[3];
    __syncthreads();
    const float inv = rsqrtf(red[0] * (1.0f / 512.0f) + 1e-5f);

    float4 gg = *(const float4*)(g + tid * 4);
    float4 bb = *(const float4*)(b + tid * 4);
    const float y0 = d0 * inv * gg.x + bb.x;
    const float y1 = d1 * inv * gg.y + bb.y;
    const float y2 = d2 * inv * gg.z + bb.z;
    const float y3 = d3 * inv * gg.w + bb.w;
    *(float4*)(outf + (size_t)row * DD + tid * 4) = make_float4(y0, y1, y2, y3);
    if (HL) {
        const size_t i = (size_t)row * 128 + tid;
        ((uint2*)oh)[i] = make_uint2(pack_h2(y0, y1), pack_h2(y2, y3));
    }
}

// ---------------------------------------------------------------------------
// Launch pipeline (graph-capturable)
// ---------------------------------------------------------------------------
extern "C" void kernel_launch(void* const* d_in, const int* in_sizes, int n_in,
                              void* d_out, int out_size)
{
    (void)in_sizes; (void)n_in; (void)out_size;
    const float* src  = (const float*)d_in[0];
    const float* wqkv = (const float*)d_in[1];
    const float* bqkv = (const float*)d_in[2];
    const float* wout = (const float*)d_in[3];
    const float* bout = (const float*)d_in[4];
    const float* ln1g = (const float*)d_in[5];
    const float* ln1b = (const float*)d_in[6];
    const float* w1   = (const float*)d_in[7];
    const float* b1   = (const float*)d_in[8];
    const float* w2   = (const float*)d_in[9];
    const float* b2   = (const float*)d_in[10];
    const float* ln2g = (const float*)d_in[11];
    const float* ln2b = (const float*)d_in[12];
    float* out = (float*)d_out;

    float *x1, *resb;
    __half *qh, *sh, *ah, *xh, *fh, *wq, *wo, *wu, *wd;
    cudaGetSymbolAddress((void**)&x1,   g_x1);
    cudaGetSymbolAddress((void**)&resb, g_resb);
    cudaGetSymbolAddress((void**)&qh,  g_qh);
    cudaGetSymbolAddress((void**)&sh,  g_sh);
    cudaGetSymbolAddress((void**)&ah,  g_ah);
    cudaGetSymbolAddress((void**)&xh,  g_xh);
    cudaGetSymbolAddress((void**)&fh,  g_fh);
    cudaGetSymbolAddress((void**)&wq,  g_wq);  cudaGetSymbolAddress((void**)&wo,  g_wo);
    cudaGetSymbolAddress((void**)&wu,  g_w1);  cudaGetSymbolAddress((void**)&wd,  g_w2);

    const int GEMM_SMEM = 2 * STAGE + 1024;
    cudaFuncSetAttribute(tc_gemm<1>, cudaFuncAttributeMaxDynamicSharedMemorySize, GEMM_SMEM);
    cudaFuncSetAttribute(tc_gemm<2>, cudaFuncAttributeMaxDynamicSharedMemorySize, GEMM_SMEM);
    cudaFuncSetAttribute(tc_gemm<3>, cudaFuncAttributeMaxDynamicSharedMemorySize, GEMM_SMEM);
    cudaFuncSetAttribute(attn_kernel, cudaFuncAttributeMaxDynamicSharedMemorySize, ATT_SMEM);

    // 0) conversions: src + weights -> fp16 planes
    cvtw_kernel<<<(MT * DD / 4 + 255) / 256, 256>>>(src,  sh, MT * DD / 4);
    cvtw_kernel<<<(D3 * DD / 4 + 255) / 256, 256>>>(wqkv, wq, D3 * DD / 4);
    cvtw_kernel<<<(DD * DD / 4 + 255) / 256, 256>>>(wout, wo, DD * DD / 4);
    cvtw_kernel<<<(DF * DD / 4 + 255) / 256, 256>>>(w1,   wu, DF * DD / 4);
    cvtw_kernel<<<(DD * DF / 4 + 255) / 256, 256>>>(w2,   wd, DD * DF / 4);

    // 1) QKV projection -> fp16 qkv
    tc_gemm<3><<<dim3(D3 / 128, MT / 128), 256, GEMM_SMEM>>>(
        sh, wq, bqkv, nullptr, nullptr, qh, D3, DD);
    // 2) HMMA windowed attention -> attn fp16 plane
    attn_kernel<<<dim3(MT / 128, 8), 256, ATT_SMEM>>>(qh, ah);
    // 3) out projection + residual(src) -> resb f32
    tc_gemm<2><<<dim3(DD / 128, MT / 128), 256, GEMM_SMEM>>>(
        ah, wo, bout, src, resb, nullptr, DD, DD);
    // 4) LayerNorm 1 -> x1 f32 + fp16 plane
    ln_kernel<true><<<MT, 128>>>(resb, ln1g, ln1b, x1, xh);
    // 5) FFN up + ReLU -> ff fp16 plane
    tc_gemm<1><<<dim3(DF / 128, MT / 128), 256, GEMM_SMEM>>>(
        xh, wu, b1, nullptr, nullptr, fh, DF, DD);
    // 6) FFN down + residual(x1) -> resb f32
    tc_gemm<2><<<dim3(DD / 128, MT / 128), 256, GEMM_SMEM>>>(
        fh, wd, b2, x1, resb, nullptr, DD, DF);
    // 7) LayerNorm 2 -> output
    ln_kernel<false><<<MT, 128>>>(resb, ln2g, ln2b, out, nullptr);
}